// round 10
// baseline (speedup 1.0000x reference)
#include <cuda_runtime.h>

#define NN 524288
#define EE 8388608
#define EV (EE/4)
#define NPG 8192
#define NB 64
#define NWORDS (NN/32)
#define CAP0 (1<<16)
#define CAP1 (1<<20)
#define CAP2 (1<<22)
#define NBLK 148
#define NTHR 1024
#define NT (NBLK*NTHR)

__device__ __align__(128) float g_deg[NN];
__device__ __align__(128) float g_hs[NN*8];
__device__ __align__(128) float g_acc1[NN*8];
__device__ __align__(128) float g_h2s[NN*8];
__device__ __align__(128) float g_acc2[NN*8];
__device__ __align__(128) float g_h3s[NN];
__device__ __align__(128) float g_acc3[NN];
__device__ unsigned g_bmG[NWORDS];
__device__ int2 g_list0[CAP0];
__device__ int2 g_list1[CAP1];
__device__ int2 g_list2[CAP2];
__device__ int g_nl1[1<<17];
__device__ int g_nl2[1<<20];
__device__ int g_nl3[NN];
__device__ int g_tn[NB];
__device__ int g_cnt0, g_cnt1, g_cnt2, g_n1, g_n2, g_n3;
__device__ int g_bar_cnt = 0;
__device__ int g_bar_gen = 0;

__device__ __forceinline__ void zero8(float* p){
  float4 z = make_float4(0.f,0.f,0.f,0.f);
  ((float4*)p)[0] = z; ((float4*)p)[1] = z;
}

__device__ __forceinline__ void gbar(){
  __syncthreads();
  if (threadIdx.x == 0){
    __threadfence();
    int gen = *((volatile int*)&g_bar_gen);
    if (atomicAdd(&g_bar_cnt, 1) == NBLK-1){
      g_bar_cnt = 0;
      __threadfence();
      *((volatile int*)&g_bar_gen) = gen + 1;
    } else {
      while (*((volatile int*)&g_bar_gen) == gen) { }
    }
    __threadfence();
  }
  __syncthreads();
}

__device__ __forceinline__ void wappend2(bool pred, int2 val, int* cnt, int2* list, int cap){
  unsigned m = __ballot_sync(0xffffffffu, pred);
  if (!m) return;
  int lane = threadIdx.x & 31;
  int leader = __ffs(m) - 1;
  int base = 0;
  if (lane == leader) base = atomicAdd(cnt, __popc(m));
  base = __shfl_sync(0xffffffffu, base, leader);
  if (pred){
    int p = base + __popc(m & ((1u<<lane)-1u));
    if (p < cap) list[p] = val;
  }
}

__device__ __forceinline__ void grow(int s, int* nl, int* n, int z1, int z2){
  unsigned bit = 1u<<(s&31);
  unsigned old = atomicOr(&g_bmG[s>>5], bit);
  if (!(old & bit)){
    int p = atomicAdd(n, 1);
    nl[p] = s;
    if (z1) zero8(g_acc1 + (size_t)s*8);
    if (z2) zero8(g_acc2 + (size_t)s*8);
  }
}

// process one int4 quad: probe smem bitmap, append (src,dst), grow frontier
__device__ __forceinline__ void quad_scan(const unsigned* sbm, int4 d, int e0, bool v,
                                          const int* __restrict__ srcp,
                                          int* cnt, int2* list, int cap,
                                          int* nl, int* n, int z1, int z2){
  bool p0 = v && ((sbm[d.x>>5]>>(d.x&31))&1u);
  bool p1 = v && ((sbm[d.y>>5]>>(d.y&31))&1u);
  bool p2 = v && ((sbm[d.z>>5]>>(d.z&31))&1u);
  bool p3 = v && ((sbm[d.w>>5]>>(d.w&31))&1u);
  if (!__ballot_sync(0xffffffffu, p0|p1|p2|p3)) return;
  int s0=0,s1=0,s2=0,s3=0;
  if (p0) s0 = srcp[e0];
  if (p1) s1 = srcp[e0+1];
  if (p2) s2 = srcp[e0+2];
  if (p3) s3 = srcp[e0+3];
  wappend2(p0, make_int2(s0,d.x), cnt, list, cap);
  wappend2(p1, make_int2(s1,d.y), cnt, list, cap);
  wappend2(p2, make_int2(s2,d.z), cnt, list, cap);
  wappend2(p3, make_int2(s3,d.w), cnt, list, cap);
  if (p0) grow(s0, nl, n, z1, z2);
  if (p1) grow(s1, nl, n, z1, z2);
  if (p2) grow(s2, nl, n, z1, z2);
  if (p3) grow(s3, nl, n, z1, z2);
}

__global__ __launch_bounds__(NTHR) void k_mega(
    const float* __restrict__ x, const int* __restrict__ srcp, const int4* __restrict__ dst4,
    const int* __restrict__ tgt,
    const float* __restrict__ W1, const float* __restrict__ b1,
    const float* __restrict__ W2, const float* __restrict__ b2,
    const float* __restrict__ W3, const float* __restrict__ b3,
    const float* __restrict__ Wl1, const float* __restrict__ bl1,
    const float* __restrict__ Wl2, const float* __restrict__ bl2,
    float* __restrict__ out){
  extern __shared__ unsigned sbm[];            // 64 KB bitmap snapshot
  __shared__ float sWT[8*132];                 // W1^T [j][k]
  __shared__ int   s_tgt[NB];
  __shared__ float sW2[64], sb1[8], sW3[8], sb2[8];
  __shared__ float sWl1[17*16], sbl1[16], sWl2[32], sbl2[2];

  int t = threadIdx.x;
  int gtid = blockIdx.x*NTHR + t;

  if (t < 1024) sWT[(t&7)*132 + (t>>3)] = W1[t];
  if (t < NB) s_tgt[t] = tgt[t];
  if (t < 64) sW2[t] = W2[t];
  if (t < 8){ sb1[t] = b1[t]; sW3[t] = W3[t]; sb2[t] = b2[t]; }
  if (t >= 64 && t < 64+272) sWl1[t-64] = Wl1[t-64];
  if (t >= 384 && t < 400) sbl1[t-384] = bl1[t-384];
  if (t >= 400 && t < 432) sWl2[t-400] = Wl2[t-400];
  if (t >= 432 && t < 434) sbl2[t-432] = bl2[t-432];
  __syncthreads();

  // ---- P0: init ----
  for (int i = gtid; i < NN; i += NT) g_deg[i] = 1.0f;
  for (int i = gtid; i < NWORDS; i += NT) g_bmG[i] = 0u;
  if (gtid == 0){ g_cnt0=0; g_cnt1=0; g_cnt2=0; g_n1=0; g_n2=0; g_n3=0; }
  gbar();

  // ---- P1: mark targets + scan0 (arithmetic test, batched MLP-4) + grow S1 ----
  if (blockIdx.x == 0 && t < NB){
    int node = t*NPG + s_tgt[t];
    g_tn[t] = node;
    unsigned bit = 1u<<(node&31);
    unsigned old = atomicOr(&g_bmG[node>>5], bit);
    if (!(old & bit)){
      int p = atomicAdd(&g_n1, 1);
      g_nl1[p] = node;
      zero8(g_acc1 + (size_t)node*8);
      zero8(g_acc2 + (size_t)node*8);
    }
    g_acc3[node] = 0.f;
  }
  for (int base = 0; base < EV; base += NT*4){
    int4 d[4]; bool v[4]; int idx[4];
    #pragma unroll
    for (int b=0;b<4;b++){
      idx[b] = base + b*NT + gtid;
      v[b] = idx[b] < EV;
      d[b] = v[b] ? dst4[idx[b]] : make_int4(0,0,0,0);
    }
    #pragma unroll
    for (int b=0;b<4;b++){
      bool p0 = v[b] && ((d[b].x & (NPG-1)) == s_tgt[d[b].x>>13]);
      bool p1 = v[b] && ((d[b].y & (NPG-1)) == s_tgt[d[b].y>>13]);
      bool p2 = v[b] && ((d[b].z & (NPG-1)) == s_tgt[d[b].z>>13]);
      bool p3 = v[b] && ((d[b].w & (NPG-1)) == s_tgt[d[b].w>>13]);
      if (!__ballot_sync(0xffffffffu, p0|p1|p2|p3)) continue;
      int e0 = 4*idx[b];
      int s0=0,s1=0,s2=0,s3=0;
      if (p0) s0 = srcp[e0];
      if (p1) s1 = srcp[e0+1];
      if (p2) s2 = srcp[e0+2];
      if (p3) s3 = srcp[e0+3];
      wappend2(p0, make_int2(s0,d[b].x), &g_cnt0, g_list0, CAP0);
      wappend2(p1, make_int2(s1,d[b].y), &g_cnt0, g_list0, CAP0);
      wappend2(p2, make_int2(s2,d[b].z), &g_cnt0, g_list0, CAP0);
      wappend2(p3, make_int2(s3,d[b].w), &g_cnt0, g_list0, CAP0);
      if (p0) grow(s0, g_nl1, &g_n1, 1, 1);
      if (p1) grow(s1, g_nl1, &g_n1, 1, 1);
      if (p2) grow(s2, g_nl1, &g_n1, 1, 1);
      if (p3) grow(s3, g_nl1, &g_n1, 1, 1);
    }
  }
  gbar();

  // ---- P2: snapshot S1, scan1 -> list1, grow S2 ----
  {
    uint4* s4 = (uint4*)sbm; const uint4* bm4 = (const uint4*)g_bmG;
    for (int i = t; i < NWORDS/4; i += NTHR) s4[i] = bm4[i];
    __syncthreads();
    for (int base = 0; base < EV; base += NT*4){
      int4 d[4]; bool v[4]; int idx[4];
      #pragma unroll
      for (int b=0;b<4;b++){
        idx[b] = base + b*NT + gtid;
        v[b] = idx[b] < EV;
        d[b] = v[b] ? dst4[idx[b]] : make_int4(0,0,0,0);
      }
      #pragma unroll
      for (int b=0;b<4;b++)
        quad_scan(sbm, d[b], 4*idx[b], v[b], srcp, &g_cnt1, g_list1, CAP1, g_nl2, &g_n2, 1, 0);
    }
  }
  gbar();

  // ---- P3: snapshot S2, scan2 -> list2, grow S3 ----
  {
    __syncthreads();
    uint4* s4 = (uint4*)sbm; const uint4* bm4 = (const uint4*)g_bmG;
    for (int i = t; i < NWORDS/4; i += NTHR) s4[i] = bm4[i];
    __syncthreads();
    for (int base = 0; base < EV; base += NT*4){
      int4 d[4]; bool v[4]; int idx[4];
      #pragma unroll
      for (int b=0;b<4;b++){
        idx[b] = base + b*NT + gtid;
        v[b] = idx[b] < EV;
        d[b] = v[b] ? dst4[idx[b]] : make_int4(0,0,0,0);
      }
      #pragma unroll
      for (int b=0;b<4;b++)
        quad_scan(sbm, d[b], 4*idx[b], v[b], srcp, &g_cnt2, g_list2, CAP2, g_nl3, &g_n3, 0, 0);
    }
  }
  gbar();

  // ---- P3b: snapshot S3, sparse degree (RED only when dst in S3) ----
  {
    __syncthreads();
    uint4* s4 = (uint4*)sbm; const uint4* bm4 = (const uint4*)g_bmG;
    for (int i = t; i < NWORDS/4; i += NTHR) s4[i] = bm4[i];
    __syncthreads();
    for (int base = 0; base < EV; base += NT*4){
      int4 d[4]; bool v[4];
      #pragma unroll
      for (int b=0;b<4;b++){
        int idx = base + b*NT + gtid;
        v[b] = idx < EV;
        d[b] = v[b] ? dst4[idx] : make_int4(0,0,0,0);
      }
      #pragma unroll
      for (int b=0;b<4;b++){
        if (v[b] && ((sbm[d[b].x>>5]>>(d[b].x&31))&1u)) atomicAdd(&g_deg[d[b].x],1.f);
        if (v[b] && ((sbm[d[b].y>>5]>>(d[b].y&31))&1u)) atomicAdd(&g_deg[d[b].y],1.f);
        if (v[b] && ((sbm[d[b].z>>5]>>(d[b].z&31))&1u)) atomicAdd(&g_deg[d[b].z],1.f);
        if (v[b] && ((sbm[d[b].w>>5]>>(d[b].w&31))&1u)) atomicAdd(&g_deg[d[b].w],1.f);
      }
    }
  }
  gbar();

  // ---- P4: sparse h1 over nl1 ++ nl2 ++ nl3 : hs = rsqrt(deg)*(x@W1) ----
  {
    int n1 = g_n1, n2 = g_n2, n3 = g_n3;
    int ntot = n1 + n2 + n3;
    int sub  = t & 7;
    int slot = gtid >> 3;
    const int nslots = NT >> 3;
    int iters = (ntot + nslots - 1)/nslots;
    for (int it = 0; it < iters; it++){
      int i = slot + it*nslots;
      bool act = i < ntot;
      int node = 0;
      if (act) node = (i < n1) ? g_nl1[i] : (i < n1+n2) ? g_nl2[i-n1] : g_nl3[i-n1-n2];
      const float* xr = x + (size_t)node*128 + sub*4;
      float4 v0 = *(const float4*)(xr);
      float4 v1 = *(const float4*)(xr + 32);
      float4 v2 = *(const float4*)(xr + 64);
      float4 v3 = *(const float4*)(xr + 96);
      float acc[8];
      #pragma unroll
      for (int j=0;j<8;j++) acc[j] = 0.f;
      #pragma unroll
      for (int q=0;q<4;q++){
        float4 xv = (q==0)?v0:(q==1)?v1:(q==2)?v2:v3;
        int kb = 32*q + 4*sub;
        #pragma unroll
        for (int j=0;j<8;j++){
          float4 wv = *(const float4*)&sWT[j*132 + kb];
          acc[j] += xv.x*wv.x + xv.y*wv.y + xv.z*wv.z + xv.w*wv.w;
        }
      }
      #pragma unroll
      for (int off=4; off; off>>=1){
        #pragma unroll
        for (int j=0;j<8;j++) acc[j] += __shfl_xor_sync(0xffffffffu, acc[j], off);
      }
      if (act && sub == 0){
        float r = rsqrtf(g_deg[node]);
        float* hp = g_hs + (size_t)node*8;
        *(float4*)hp     = make_float4(acc[0]*r,acc[1]*r,acc[2]*r,acc[3]*r);
        *(float4*)(hp+4) = make_float4(acc[4]*r,acc[5]*r,acc[6]*r,acc[7]*r);
      }
    }
  }
  gbar();

  // ---- P5: agg1 over list2 ----
  {
    int n = min(g_cnt2, CAP2);
    for (int i = gtid; i < n; i += NT){
      int2 sd = g_list2[i];
      const float* hp = g_hs + (size_t)sd.x*8;
      float4 a = *(const float4*)hp, b = *(const float4*)(hp+4);
      float* ap = g_acc1 + (size_t)sd.y*8;
      atomicAdd((float4*)ap, a);
      atomicAdd((float4*)(ap+4), b);
    }
  }
  gbar();

  // ---- P6: h2 over nl1 ++ nl2 ----
  {
    int n1 = g_n1, n2 = g_n2;
    int nS2 = n1 + n2;
    for (int i = gtid; i < nS2; i += NT){
      int node = (i < n1) ? g_nl1[i] : g_nl2[i - n1];
      float r = rsqrtf(g_deg[node]);
      const float* ap = g_acc1 + (size_t)node*8;
      const float* hp = g_hs  + (size_t)node*8;
      float x1[8];
      #pragma unroll
      for (int j=0;j<8;j++) x1[j] = fmaxf(r*(ap[j]+hp[j]) + sb1[j], 0.f);
      float* h2p = g_h2s + (size_t)node*8;
      #pragma unroll
      for (int j=0;j<8;j++){
        float s2 = 0.f;
        #pragma unroll
        for (int u=0;u<8;u++) s2 += x1[u]*sW2[u*8+j];
        h2p[j] = r*s2;
      }
    }
  }
  gbar();

  // ---- P7: agg2 over list1 ----
  {
    int n = min(g_cnt1, CAP1);
    for (int i = gtid; i < n; i += NT){
      int2 sd = g_list1[i];
      const float* hp = g_h2s + (size_t)sd.x*8;
      float4 a = *(const float4*)hp, b = *(const float4*)(hp+4);
      float* ap = g_acc2 + (size_t)sd.y*8;
      atomicAdd((float4*)ap, a);
      atomicAdd((float4*)(ap+4), b);
    }
  }
  gbar();

  // ---- P8: h3 over nl1 ----
  {
    int n1 = g_n1;
    for (int i = gtid; i < n1; i += NT){
      int node = g_nl1[i];
      float r = rsqrtf(g_deg[node]);
      const float* ap = g_acc2 + (size_t)node*8;
      const float* hp = g_h2s + (size_t)node*8;
      float s2 = 0.f;
      #pragma unroll
      for (int j=0;j<8;j++) s2 += fmaxf(r*(ap[j]+hp[j]) + sb2[j], 0.f)*sW3[j];
      g_h3s[node] = r*s2;
    }
  }
  gbar();

  // ---- P9: agg3 over list0 ----
  {
    int n = min(g_cnt0, CAP0);
    for (int i = gtid; i < n; i += NT){
      int2 sd = g_list0[i];
      atomicAdd(&g_acc3[sd.y], g_h3s[sd.x]);
    }
  }
  gbar();

  // ---- P10: head ----
  if (blockIdx.x == 0 && t < NB){
    int node = g_tn[t];
    float r = rsqrtf(g_deg[node]);
    float f[17];
    const float* a1 = g_acc1 + (size_t)node*8;
    const float* h1 = g_hs  + (size_t)node*8;
    const float* a2 = g_acc2 + (size_t)node*8;
    const float* h2 = g_h2s + (size_t)node*8;
    #pragma unroll
    for (int j=0;j<8;j++) f[j]   = fmaxf(r*(a1[j]+h1[j]) + sb1[j], 0.f);
    #pragma unroll
    for (int j=0;j<8;j++) f[8+j] = fmaxf(r*(a2[j]+h2[j]) + sb2[j], 0.f);
    f[16] = fmaxf(r*(g_acc3[node]+g_h3s[node]) + b3[0], 0.f);
    float z[16];
    #pragma unroll
    for (int j=0;j<16;j++){
      float s2 = sbl1[j];
      #pragma unroll
      for (int u=0;u<17;u++) s2 += f[u]*sWl1[u*16+j];
      z[j] = fmaxf(s2, 0.f);
    }
    #pragma unroll
    for (int o=0;o<2;o++){
      float s2 = sbl2[o];
      #pragma unroll
      for (int u=0;u<16;u++) s2 += z[u]*sWl2[u*2+o];
      out[t*2+o] = s2;
    }
  }
}

extern "C" void kernel_launch(void* const* d_in, const int* in_sizes, int n_in,
                              void* d_out, int out_size){
  const float* x    = (const float*)d_in[0];
  const int*   ei   = (const int*)  d_in[1];
  const int*   tgt  = (const int*)  d_in[2];
  const float* W1   = (const float*)d_in[3];
  const float* b1   = (const float*)d_in[4];
  const float* W2   = (const float*)d_in[5];
  const float* b2   = (const float*)d_in[6];
  const float* W3   = (const float*)d_in[7];
  const float* b3   = (const float*)d_in[8];
  const float* Wl1  = (const float*)d_in[9];
  const float* bl1  = (const float*)d_in[10];
  const float* Wl2  = (const float*)d_in[11];
  const float* bl2  = (const float*)d_in[12];
  const int* srcp = ei;
  const int4* dst4 = (const int4*)(ei + EE);
  float* out = (float*)d_out;

  cudaFuncSetAttribute(k_mega, cudaFuncAttributeMaxDynamicSharedMemorySize, NWORDS*4);
  k_mega<<<NBLK, NTHR, NWORDS*4>>>(x, srcp, dst4, tgt,
                                   W1, b1, W2, b2, W3, b3,
                                   Wl1, bl1, Wl2, bl2, out);
}

// round 12
// speedup vs baseline: 1.6800x; 1.6800x over previous
#include <cuda_runtime.h>

#define NN 524288
#define EE 8388608
#define EV (EE/4)
#define NPG 8192
#define NB 64
#define NWORDS (NN/32)
#define CAP0 (1<<16)
#define CAP1 (1<<20)
#define CAP2 (1<<22)
#define NBLK 148
#define NTHR 1024
#define NT (NBLK*NTHR)
#define SCAP 4096

__device__ __align__(128) float g_deg[NN];
__device__ __align__(128) float g_hs[NN*8];
__device__ __align__(128) float g_acc1[NN*8];
__device__ __align__(128) float g_h2s[NN*8];
__device__ __align__(128) float g_acc2[NN*8];
__device__ __align__(128) float g_h3s[NN];
__device__ __align__(128) float g_acc3[NN];
__device__ __align__(128) unsigned g_bmG[NWORDS];
__device__ __align__(128) int2 g_list0[CAP0];
__device__ __align__(128) int2 g_list1[CAP1];
__device__ __align__(128) int2 g_list2[CAP2];
__device__ int g_nlS1[1<<17];
__device__ int g_nlS2[1<<20];
__device__ int g_nlS3[NN];
__device__ int g_tn[NB];
__device__ int g_cnt0, g_cnt1, g_cnt2, g_nS1, g_nS2, g_nS3;
__device__ int g_bar_cnt = 0;
__device__ int g_bar_gen = 0;

__device__ __forceinline__ void zero8(float* p){
  float4 z = make_float4(0.f,0.f,0.f,0.f);
  ((float4*)p)[0] = z; ((float4*)p)[1] = z;
}

__device__ __forceinline__ void gbar(){
  __syncthreads();
  if (threadIdx.x == 0){
    __threadfence();
    int gen = *((volatile int*)&g_bar_gen);
    if (atomicAdd(&g_bar_cnt, 1) == NBLK-1){
      g_bar_cnt = 0;
      __threadfence();
      *((volatile int*)&g_bar_gen) = gen + 1;
    } else {
      while (*((volatile int*)&g_bar_gen) == gen) { }
    }
    __threadfence();
  }
  __syncthreads();
}

// stage an append into smem buffer; overflow -> direct global (rare)
__device__ __forceinline__ void stage2(bool pred, int2 val, int* scnt, int2* sbuf,
                                       int* gcnt, int2* glist, int gcap){
  unsigned m = __ballot_sync(0xffffffffu, pred);
  if (!m) return;
  int lane = threadIdx.x & 31;
  int leader = __ffs(m) - 1;
  int base = 0;
  if (lane == leader) base = atomicAdd(scnt, __popc(m));
  base = __shfl_sync(0xffffffffu, base, leader);
  if (pred){
    int pos = base + __popc(m & ((1u<<lane)-1u));
    if (pos < SCAP) sbuf[pos] = val;
    else { int g = atomicAdd(gcnt, 1); if (g < gcap) glist[g] = val; }
  }
}

// block-wide flush of staging buffer
__device__ __forceinline__ void flush(int* scnt, int2* sbuf, int* sbase,
                                      int* gcnt, int2* glist, int gcap){
  __syncthreads();
  int c = min(*scnt, SCAP);
  if (c > 0){
    if (threadIdx.x == 0) *sbase = atomicAdd(gcnt, c);
    __syncthreads();
    int b = *sbase;
    for (int i = threadIdx.x; i < c; i += NTHR)
      if (b + i < gcap) glist[b + i] = sbuf[i];
  }
  __syncthreads();
  if (threadIdx.x == 0) *scnt = 0;
  __syncthreads();
}

// dense bitmap compaction: bmG -> list, optional acc zeroing. warp-aggregated counter.
__device__ __forceinline__ void compact(int gtid, int* outlist, int* outcnt,
                                        float* zA, float* zB){
  int lane = threadIdx.x & 31;
  for (int wi = gtid; wi < NWORDS; wi += NT){
    unsigned bits = g_bmG[wi];
    int c = __popc(bits);
    int pre = c;
    #pragma unroll
    for (int off=1; off<32; off<<=1){
      int nv = __shfl_up_sync(0xffffffffu, pre, off);
      if (lane >= off) pre += nv;
    }
    int tot = __shfl_sync(0xffffffffu, pre, 31);
    int excl = pre - c;
    int base = 0;
    if (lane == 31 && tot) base = atomicAdd(outcnt, tot);
    base = __shfl_sync(0xffffffffu, base, 31);
    int pos = base + excl;
    while (bits){
      int b = __ffs(bits) - 1; bits &= bits - 1;
      int node = wi*32 + b;
      outlist[pos++] = node;
      if (zA) zero8(zA + (size_t)node*8);
      if (zB) zero8(zB + (size_t)node*8);
    }
  }
}

__global__ __launch_bounds__(NTHR) void k_mega(
    const float* __restrict__ x, const int* __restrict__ srcp, const int4* __restrict__ dst4,
    const int* __restrict__ tgt,
    const float* __restrict__ W1, const float* __restrict__ b1,
    const float* __restrict__ W2, const float* __restrict__ b2,
    const float* __restrict__ W3, const float* __restrict__ b3,
    const float* __restrict__ Wl1, const float* __restrict__ bl1,
    const float* __restrict__ Wl2, const float* __restrict__ bl2,
    float* __restrict__ out){
  extern __shared__ __align__(16) unsigned sbm[];   // 64 KB bitmap snapshot
  __shared__ __align__(16) int2  s_stage[SCAP];     // 32 KB staging
  __shared__ __align__(16) float sWT[8*132];        // W1^T [j][k]
  __shared__ int   s_scnt, s_base;
  __shared__ int   s_tgt[NB];
  __shared__ float sW2[64], sb1[8], sW3[8], sb2[8];
  __shared__ float sWl1[17*16], sbl1[16], sWl2[32], sbl2[2];

  int t = threadIdx.x;
  int gtid = blockIdx.x*NTHR + t;

  if (t < 1024) sWT[(t&7)*132 + (t>>3)] = W1[t];
  if (t < NB) s_tgt[t] = tgt[t];
  if (t < 64) sW2[t] = W2[t];
  if (t < 8){ sb1[t] = b1[t]; sW3[t] = W3[t]; sb2[t] = b2[t]; }
  if (t >= 64 && t < 64+272) sWl1[t-64] = Wl1[t-64];
  if (t >= 384 && t < 400) sbl1[t-384] = bl1[t-384];
  if (t >= 400 && t < 432) sWl2[t-400] = Wl2[t-400];
  if (t >= 432 && t < 434) sbl2[t-432] = bl2[t-432];
  if (t == 0) s_scnt = 0;
  __syncthreads();

  // ---- P0: init ----
  for (int i = gtid; i < NN; i += NT) g_deg[i] = 1.0f;
  for (int i = gtid; i < NWORDS; i += NT) g_bmG[i] = 0u;
  if (gtid == 0){ g_cnt0=0; g_cnt1=0; g_cnt2=0; g_nS1=0; g_nS2=0; g_nS3=0; }
  gbar();

  // ---- P1: mark targets; scan0 (arithmetic test): list0 + src bits ----
  if (blockIdx.x == 0 && t < NB){
    int node = t*NPG + s_tgt[t];
    g_tn[t] = node;
    atomicOr(&g_bmG[node>>5], 1u<<(node&31));
    g_acc3[node] = 0.f;
  }
  for (int base = 0; base < EV; base += NT*4){
    int4 d[4]; bool v[4]; int idx[4];
    #pragma unroll
    for (int b=0;b<4;b++){
      idx[b] = base + b*NT + gtid;
      v[b] = idx[b] < EV;
      d[b] = v[b] ? dst4[idx[b]] : make_int4(0,0,0,0);
    }
    #pragma unroll
    for (int b=0;b<4;b++){
      bool p0 = v[b] && ((d[b].x & (NPG-1)) == s_tgt[d[b].x>>13]);
      bool p1 = v[b] && ((d[b].y & (NPG-1)) == s_tgt[d[b].y>>13]);
      bool p2 = v[b] && ((d[b].z & (NPG-1)) == s_tgt[d[b].z>>13]);
      bool p3 = v[b] && ((d[b].w & (NPG-1)) == s_tgt[d[b].w>>13]);
      if (!__ballot_sync(0xffffffffu, p0|p1|p2|p3)) continue;
      int e0 = 4*idx[b];
      int s0=0,s1=0,s2=0,s3=0;
      if (p0){ s0 = srcp[e0];   atomicOr(&g_bmG[s0>>5], 1u<<(s0&31)); }
      if (p1){ s1 = srcp[e0+1]; atomicOr(&g_bmG[s1>>5], 1u<<(s1&31)); }
      if (p2){ s2 = srcp[e0+2]; atomicOr(&g_bmG[s2>>5], 1u<<(s2&31)); }
      if (p3){ s3 = srcp[e0+3]; atomicOr(&g_bmG[s3>>5], 1u<<(s3&31)); }
      stage2(p0, make_int2(s0,d[b].x), &s_scnt, s_stage, &g_cnt0, g_list0, CAP0);
      stage2(p1, make_int2(s1,d[b].y), &s_scnt, s_stage, &g_cnt0, g_list0, CAP0);
      stage2(p2, make_int2(s2,d[b].z), &s_scnt, s_stage, &g_cnt0, g_list0, CAP0);
      stage2(p3, make_int2(s3,d[b].w), &s_scnt, s_stage, &g_cnt0, g_list0, CAP0);
    }
    flush(&s_scnt, s_stage, &s_base, &g_cnt0, g_list0, CAP0);
  }
  gbar();

  // ---- C1: compact S1 -> nlS1, zero acc2 on S1 ----
  compact(gtid, g_nlS1, &g_nS1, g_acc2, 0);
  gbar();

  // ---- P2: snapshot S1; scan1 -> list1 + grow bits to S2 ----
  {
    uint4* s4 = (uint4*)sbm; const uint4* bm4 = (const uint4*)g_bmG;
    for (int i = t; i < NWORDS/4; i += NTHR) s4[i] = bm4[i];
    __syncthreads();
    for (int base = 0; base < EV; base += NT*4){
      int4 d[4]; bool v[4]; int idx[4];
      #pragma unroll
      for (int b=0;b<4;b++){
        idx[b] = base + b*NT + gtid;
        v[b] = idx[b] < EV;
        d[b] = v[b] ? dst4[idx[b]] : make_int4(0,0,0,0);
      }
      #pragma unroll
      for (int b=0;b<4;b++){
        bool p0 = v[b] && ((sbm[d[b].x>>5]>>(d[b].x&31))&1u);
        bool p1 = v[b] && ((sbm[d[b].y>>5]>>(d[b].y&31))&1u);
        bool p2 = v[b] && ((sbm[d[b].z>>5]>>(d[b].z&31))&1u);
        bool p3 = v[b] && ((sbm[d[b].w>>5]>>(d[b].w&31))&1u);
        if (!__ballot_sync(0xffffffffu, p0|p1|p2|p3)) continue;
        int e0 = 4*idx[b];
        int s0=0,s1=0,s2=0,s3=0;
        if (p0){ s0 = srcp[e0];   atomicOr(&g_bmG[s0>>5], 1u<<(s0&31)); }
        if (p1){ s1 = srcp[e0+1]; atomicOr(&g_bmG[s1>>5], 1u<<(s1&31)); }
        if (p2){ s2 = srcp[e0+2]; atomicOr(&g_bmG[s2>>5], 1u<<(s2&31)); }
        if (p3){ s3 = srcp[e0+3]; atomicOr(&g_bmG[s3>>5], 1u<<(s3&31)); }
        stage2(p0, make_int2(s0,d[b].x), &s_scnt, s_stage, &g_cnt1, g_list1, CAP1);
        stage2(p1, make_int2(s1,d[b].y), &s_scnt, s_stage, &g_cnt1, g_list1, CAP1);
        stage2(p2, make_int2(s2,d[b].z), &s_scnt, s_stage, &g_cnt1, g_list1, CAP1);
        stage2(p3, make_int2(s3,d[b].w), &s_scnt, s_stage, &g_cnt1, g_list1, CAP1);
      }
      flush(&s_scnt, s_stage, &s_base, &g_cnt1, g_list1, CAP1);
    }
  }
  gbar();

  // ---- C2: compact S2 -> nlS2, zero acc1 on S2 ----
  compact(gtid, g_nlS2, &g_nS2, g_acc1, 0);
  gbar();

  // ---- P3: snapshot S2; scan2 -> list2 + grow bits to S3 ----
  {
    __syncthreads();
    uint4* s4 = (uint4*)sbm; const uint4* bm4 = (const uint4*)g_bmG;
    for (int i = t; i < NWORDS/4; i += NTHR) s4[i] = bm4[i];
    __syncthreads();
    for (int base = 0; base < EV; base += NT*4){
      int4 d[4]; bool v[4]; int idx[4];
      #pragma unroll
      for (int b=0;b<4;b++){
        idx[b] = base + b*NT + gtid;
        v[b] = idx[b] < EV;
        d[b] = v[b] ? dst4[idx[b]] : make_int4(0,0,0,0);
      }
      #pragma unroll
      for (int b=0;b<4;b++){
        bool p0 = v[b] && ((sbm[d[b].x>>5]>>(d[b].x&31))&1u);
        bool p1 = v[b] && ((sbm[d[b].y>>5]>>(d[b].y&31))&1u);
        bool p2 = v[b] && ((sbm[d[b].z>>5]>>(d[b].z&31))&1u);
        bool p3 = v[b] && ((sbm[d[b].w>>5]>>(d[b].w&31))&1u);
        if (!__ballot_sync(0xffffffffu, p0|p1|p2|p3)) continue;
        int e0 = 4*idx[b];
        int s0=0,s1=0,s2=0,s3=0;
        if (p0){ s0 = srcp[e0];   atomicOr(&g_bmG[s0>>5], 1u<<(s0&31)); }
        if (p1){ s1 = srcp[e0+1]; atomicOr(&g_bmG[s1>>5], 1u<<(s1&31)); }
        if (p2){ s2 = srcp[e0+2]; atomicOr(&g_bmG[s2>>5], 1u<<(s2&31)); }
        if (p3){ s3 = srcp[e0+3]; atomicOr(&g_bmG[s3>>5], 1u<<(s3&31)); }
        stage2(p0, make_int2(s0,d[b].x), &s_scnt, s_stage, &g_cnt2, g_list2, CAP2);
        stage2(p1, make_int2(s1,d[b].y), &s_scnt, s_stage, &g_cnt2, g_list2, CAP2);
        stage2(p2, make_int2(s2,d[b].z), &s_scnt, s_stage, &g_cnt2, g_list2, CAP2);
        stage2(p3, make_int2(s3,d[b].w), &s_scnt, s_stage, &g_cnt2, g_list2, CAP2);
      }
      flush(&s_scnt, s_stage, &s_base, &g_cnt2, g_list2, CAP2);
    }
  }
  gbar();

  // ---- P3b: compact S3 -> nlS3; snapshot S3; sparse degree ----
  compact(gtid, g_nlS3, &g_nS3, 0, 0);
  {
    __syncthreads();
    uint4* s4 = (uint4*)sbm; const uint4* bm4 = (const uint4*)g_bmG;
    for (int i = t; i < NWORDS/4; i += NTHR) s4[i] = bm4[i];
    __syncthreads();
    for (int base = 0; base < EV; base += NT*4){
      int4 d[4]; bool v[4];
      #pragma unroll
      for (int b=0;b<4;b++){
        int idx = base + b*NT + gtid;
        v[b] = idx < EV;
        d[b] = v[b] ? dst4[idx] : make_int4(0,0,0,0);
      }
      #pragma unroll
      for (int b=0;b<4;b++){
        if (v[b] && ((sbm[d[b].x>>5]>>(d[b].x&31))&1u)) atomicAdd(&g_deg[d[b].x],1.f);
        if (v[b] && ((sbm[d[b].y>>5]>>(d[b].y&31))&1u)) atomicAdd(&g_deg[d[b].y],1.f);
        if (v[b] && ((sbm[d[b].z>>5]>>(d[b].z&31))&1u)) atomicAdd(&g_deg[d[b].z],1.f);
        if (v[b] && ((sbm[d[b].w>>5]>>(d[b].w&31))&1u)) atomicAdd(&g_deg[d[b].w],1.f);
      }
    }
  }
  gbar();

  // ---- P4: sparse h1 over nlS3: hs = rsqrt(deg)*(x@W1) ----
  {
    int ntot = min(g_nS3, NN);
    int sub  = t & 7;
    int slot = gtid >> 3;
    const int nslots = NT >> 3;
    int iters = (ntot + nslots - 1)/nslots;
    for (int it = 0; it < iters; it++){
      int i = slot + it*nslots;
      bool act = i < ntot;
      int node = act ? g_nlS3[i] : 0;
      const float* xr = x + (size_t)node*128 + sub*4;
      float4 v0 = *(const float4*)(xr);
      float4 v1 = *(const float4*)(xr + 32);
      float4 v2 = *(const float4*)(xr + 64);
      float4 v3 = *(const float4*)(xr + 96);
      float acc[8];
      #pragma unroll
      for (int j=0;j<8;j++) acc[j] = 0.f;
      #pragma unroll
      for (int q=0;q<4;q++){
        float4 xv = (q==0)?v0:(q==1)?v1:(q==2)?v2:v3;
        int kb = 32*q + 4*sub;
        #pragma unroll
        for (int j=0;j<8;j++){
          float4 wv = *(const float4*)&sWT[j*132 + kb];
          acc[j] += xv.x*wv.x + xv.y*wv.y + xv.z*wv.z + xv.w*wv.w;
        }
      }
      #pragma unroll
      for (int off=4; off; off>>=1){
        #pragma unroll
        for (int j=0;j<8;j++) acc[j] += __shfl_xor_sync(0xffffffffu, acc[j], off);
      }
      if (act && sub == 0){
        float r = rsqrtf(g_deg[node]);
        float* hp = g_hs + (size_t)node*8;
        *(float4*)hp     = make_float4(acc[0]*r,acc[1]*r,acc[2]*r,acc[3]*r);
        *(float4*)(hp+4) = make_float4(acc[4]*r,acc[5]*r,acc[6]*r,acc[7]*r);
      }
    }
  }
  gbar();

  // ---- P5: agg1 over list2 ----
  {
    int n = min(g_cnt2, CAP2);
    for (int i = gtid; i < n; i += NT){
      int2 sd = g_list2[i];
      const float* hp = g_hs + (size_t)sd.x*8;
      float4 a = *(const float4*)hp, b = *(const float4*)(hp+4);
      float* ap = g_acc1 + (size_t)sd.y*8;
      atomicAdd((float4*)ap, a);
      atomicAdd((float4*)(ap+4), b);
    }
  }
  gbar();

  // ---- P6: h2 over nlS2 ----
  {
    int n = min(g_nS2, NN);
    for (int i = gtid; i < n; i += NT){
      int node = g_nlS2[i];
      float r = rsqrtf(g_deg[node]);
      const float* ap = g_acc1 + (size_t)node*8;
      const float* hp = g_hs  + (size_t)node*8;
      float x1[8];
      #pragma unroll
      for (int j=0;j<8;j++) x1[j] = fmaxf(r*(ap[j]+hp[j]) + sb1[j], 0.f);
      float* h2p = g_h2s + (size_t)node*8;
      #pragma unroll
      for (int j=0;j<8;j++){
        float s2 = 0.f;
        #pragma unroll
        for (int u=0;u<8;u++) s2 += x1[u]*sW2[u*8+j];
        h2p[j] = r*s2;
      }
    }
  }
  gbar();

  // ---- P7: agg2 over list1 ----
  {
    int n = min(g_cnt1, CAP1);
    for (int i = gtid; i < n; i += NT){
      int2 sd = g_list1[i];
      const float* hp = g_h2s + (size_t)sd.x*8;
      float4 a = *(const float4*)hp, b = *(const float4*)(hp+4);
      float* ap = g_acc2 + (size_t)sd.y*8;
      atomicAdd((float4*)ap, a);
      atomicAdd((float4*)(ap+4), b);
    }
  }
  gbar();

  // ---- P8: h3 over nlS1 ----
  {
    int n = min(g_nS1, NN);
    for (int i = gtid; i < n; i += NT){
      int node = g_nlS1[i];
      float r = rsqrtf(g_deg[node]);
      const float* ap = g_acc2 + (size_t)node*8;
      const float* hp = g_h2s + (size_t)node*8;
      float s2 = 0.f;
      #pragma unroll
      for (int j=0;j<8;j++) s2 += fmaxf(r*(ap[j]+hp[j]) + sb2[j], 0.f)*sW3[j];
      g_h3s[node] = r*s2;
    }
  }
  gbar();

  // ---- P9: agg3 over list0 ----
  {
    int n = min(g_cnt0, CAP0);
    for (int i = gtid; i < n; i += NT){
      int2 sd = g_list0[i];
      atomicAdd(&g_acc3[sd.y], g_h3s[sd.x]);
    }
  }
  gbar();

  // ---- P10: head ----
  if (blockIdx.x == 0 && t < NB){
    int node = g_tn[t];
    float r = rsqrtf(g_deg[node]);
    float f[17];
    const float* a1 = g_acc1 + (size_t)node*8;
    const float* h1 = g_hs  + (size_t)node*8;
    const float* a2 = g_acc2 + (size_t)node*8;
    const float* h2 = g_h2s + (size_t)node*8;
    #pragma unroll
    for (int j=0;j<8;j++) f[j]   = fmaxf(r*(a1[j]+h1[j]) + sb1[j], 0.f);
    #pragma unroll
    for (int j=0;j<8;j++) f[8+j] = fmaxf(r*(a2[j]+h2[j]) + sb2[j], 0.f);
    f[16] = fmaxf(r*(g_acc3[node]+g_h3s[node]) + b3[0], 0.f);
    float z[16];
    #pragma unroll
    for (int j=0;j<16;j++){
      float s2 = sbl1[j];
      #pragma unroll
      for (int u=0;u<17;u++) s2 += f[u]*sWl1[u*16+j];
      z[j] = fmaxf(s2, 0.f);
    }
    #pragma unroll
    for (int o=0;o<2;o++){
      float s2 = sbl2[o];
      #pragma unroll
      for (int u=0;u<16;u++) s2 += z[u]*sWl2[u*2+o];
      out[t*2+o] = s2;
    }
  }
}

extern "C" void kernel_launch(void* const* d_in, const int* in_sizes, int n_in,
                              void* d_out, int out_size){
  const float* x    = (const float*)d_in[0];
  const int*   ei   = (const int*)  d_in[1];
  const int*   tgt  = (const int*)  d_in[2];
  const float* W1   = (const float*)d_in[3];
  const float* b1   = (const float*)d_in[4];
  const float* W2   = (const float*)d_in[5];
  const float* b2   = (const float*)d_in[6];
  const float* W3   = (const float*)d_in[7];
  const float* b3   = (const float*)d_in[8];
  const float* Wl1  = (const float*)d_in[9];
  const float* bl1  = (const float*)d_in[10];
  const float* Wl2  = (const float*)d_in[11];
  const float* bl2  = (const float*)d_in[12];
  const int* srcp = ei;
  const int4* dst4 = (const int4*)(ei + EE);
  float* out = (float*)d_out;

  cudaFuncSetAttribute(k_mega, cudaFuncAttributeMaxDynamicSharedMemorySize, NWORDS*4);
  k_mega<<<NBLK, NTHR, NWORDS*4>>>(x, srcp, dst4, tgt,
                                   W1, b1, W2, b2, W3, b3,
                                   Wl1, bl1, Wl2, bl2, out);
}